// round 1
// baseline (speedup 1.0000x reference)
#include <cuda_runtime.h>
#include <cuda_bf16.h>

// Problem: CausalAttention  B=4, S=2048, D_IN=D_OUT=1024
// Inputs:  x[4,2048,1024] f32, W_query[1024,1024], W_key[1024,1024], W_value[1024,1024]
// Output:  d_out = [ context_vectors (4*2048*1024 f32) | attn_scores (4*2048*2048 f32) ]

#define Bb   4
#define Ss   2048
#define Dd   1024
#define BSs  (Bb*Ss)          // 8192 tokens total

// Scratch for Q, K, V (device globals: allowed; no runtime allocation)
__device__ float g_Q[(size_t)BSs * Dd];
__device__ float g_K[(size_t)BSs * Dd];
__device__ float g_V[(size_t)BSs * Dd];

// ---------------------------------------------------------------------------
// Kernel 1: fused QKV projection.
// C[m, n_global] = sum_k X[m,k] * Wsel[k, n_local], n_global in [0,3072).
// 64x64 output tile, BK=16, 256 threads, 4x4 register tile per thread.
// ---------------------------------------------------------------------------
__global__ __launch_bounds__(256) void qkv_kernel(
    const float* __restrict__ X,
    const float* __restrict__ Wq,
    const float* __restrict__ Wk,
    const float* __restrict__ Wv)
{
    __shared__ float Xs[16][64];   // [k][m]  (transposed)
    __shared__ float Ws[16][64];   // [k][n]

    const int m0   = blockIdx.y * 64;
    const int nblk = blockIdx.x;                 // 0..47
    const int widx = (nblk * 64) / 1024;         // which weight matrix
    const int col0 = (nblk * 64) % 1024;

    const float* W   = (widx == 0) ? Wq : (widx == 1) ? Wk : Wv;
    float*       Out = (widx == 0) ? g_Q : (widx == 1) ? g_K : g_V;

    const int tid = threadIdx.x;
    const int tx  = tid & 15;
    const int ty  = tid >> 4;

    float acc[4][4] = {};

    for (int k0 = 0; k0 < Dd; k0 += 16) {
        // X tile (64 rows x 16 k) -> transposed into Xs[k][m]
        {
            const int r  = tid >> 2;          // 0..63
            const int c4 = (tid & 3) * 4;     // 0,4,8,12
            float4 v = *(const float4*)&X[(size_t)(m0 + r) * Dd + k0 + c4];
            Xs[c4 + 0][r] = v.x; Xs[c4 + 1][r] = v.y;
            Xs[c4 + 2][r] = v.z; Xs[c4 + 3][r] = v.w;
        }
        // W tile (16 k x 64 n) -> direct
        {
            const int r  = tid >> 4;          // 0..15
            const int c4 = (tid & 15) * 4;
            *(float4*)&Ws[r][c4] = *(const float4*)&W[(size_t)(k0 + r) * Dd + col0 + c4];
        }
        __syncthreads();

        #pragma unroll
        for (int kk = 0; kk < 16; kk++) {
            float4 av = *(const float4*)&Xs[kk][ty * 4];
            float4 bv = *(const float4*)&Ws[kk][tx * 4];
            float a[4] = {av.x, av.y, av.z, av.w};
            float b[4] = {bv.x, bv.y, bv.z, bv.w};
            #pragma unroll
            for (int i = 0; i < 4; i++)
                #pragma unroll
                for (int j = 0; j < 4; j++)
                    acc[i][j] += a[i] * b[j];
        }
        __syncthreads();
    }

    #pragma unroll
    for (int i = 0; i < 4; i++) {
        const int m = m0 + ty * 4 + i;
        float4 v = {acc[i][0], acc[i][1], acc[i][2], acc[i][3]};
        *(float4*)&Out[(size_t)m * Dd + col0 + tx * 4] = v;
    }
}

// ---------------------------------------------------------------------------
// Kernel 2: masked scaled scores  S[b,q,k] = (Q[b,q,:] . K[b,k,:]) / 32,
// 0 where k > q. Tiles entirely above the diagonal write zeros and skip.
// ---------------------------------------------------------------------------
__global__ __launch_bounds__(256) void scores_kernel(float* __restrict__ Sout)
{
    const int b  = blockIdx.z;
    const int q0 = blockIdx.y * 64;
    const int k0 = blockIdx.x * 64;
    const int tid = threadIdx.x;
    const int tx  = tid & 15;
    const int ty  = tid >> 4;

    float* Sb = Sout + (size_t)b * Ss * Ss;

    if (k0 > q0 + 63) {                     // fully masked tile
        const float4 z = {0.f, 0.f, 0.f, 0.f};
        #pragma unroll
        for (int i = 0; i < 4; i++) {
            const int q = q0 + ty * 4 + i;
            *(float4*)&Sb[(size_t)q * Ss + k0 + tx * 4] = z;
        }
        return;
    }

    const float* Q = g_Q + (size_t)b * Ss * Dd;
    const float* K = g_K + (size_t)b * Ss * Dd;

    __shared__ float Qs[16][64];   // [d][q]
    __shared__ float Ks[16][64];   // [d][k]

    float acc[4][4] = {};

    for (int d0 = 0; d0 < Dd; d0 += 16) {
        {
            const int r  = tid >> 2;
            const int c4 = (tid & 3) * 4;
            float4 v = *(const float4*)&Q[(size_t)(q0 + r) * Dd + d0 + c4];
            Qs[c4 + 0][r] = v.x; Qs[c4 + 1][r] = v.y;
            Qs[c4 + 2][r] = v.z; Qs[c4 + 3][r] = v.w;
            float4 w = *(const float4*)&K[(size_t)(k0 + r) * Dd + d0 + c4];
            Ks[c4 + 0][r] = w.x; Ks[c4 + 1][r] = w.y;
            Ks[c4 + 2][r] = w.z; Ks[c4 + 3][r] = w.w;
        }
        __syncthreads();

        #pragma unroll
        for (int kk = 0; kk < 16; kk++) {
            float4 av = *(const float4*)&Qs[kk][ty * 4];
            float4 bv = *(const float4*)&Ks[kk][tx * 4];
            float a[4] = {av.x, av.y, av.z, av.w};
            float b2[4] = {bv.x, bv.y, bv.z, bv.w};
            #pragma unroll
            for (int i = 0; i < 4; i++)
                #pragma unroll
                for (int j = 0; j < 4; j++)
                    acc[i][j] += a[i] * b2[j];
        }
        __syncthreads();
    }

    const float scale = 0.03125f;  // 1/sqrt(1024)
    #pragma unroll
    for (int i = 0; i < 4; i++) {
        const int q = q0 + ty * 4 + i;
        #pragma unroll
        for (int j = 0; j < 4; j++) {
            const int k = k0 + tx * 4 + j;
            Sb[(size_t)q * Ss + k] = (k <= q) ? acc[i][j] * scale : 0.0f;
        }
    }
}

// ---------------------------------------------------------------------------
// Kernel 3: row softmax over the valid causal prefix [0..q], in place.
// One block (256 threads) per row; row length <= 2048 -> 8 regs/thread cache.
// ---------------------------------------------------------------------------
__global__ __launch_bounds__(256) void softmax_kernel(float* __restrict__ Sc)
{
    const int row = blockIdx.x;            // 0..8191
    const int b = row / Ss;
    const int q = row - b * Ss;
    float* r = Sc + (size_t)b * Ss * Ss + (size_t)q * Ss;
    const int len = q + 1;
    const int t = threadIdx.x;

    __shared__ float red[256];

    float vals[8];
    int   n = 0;
    float m = -3.4e38f;
    for (int i = t; i < len; i += 256) {
        float v = r[i];
        vals[n++] = v;
        m = fmaxf(m, v);
    }
    red[t] = m; __syncthreads();
    #pragma unroll
    for (int s2 = 128; s2 > 0; s2 >>= 1) {
        if (t < s2) red[t] = fmaxf(red[t], red[t + s2]);
        __syncthreads();
    }
    m = red[0]; __syncthreads();

    float sum = 0.f;
    for (int i = 0; i < n; i++) {
        vals[i] = __expf(vals[i] - m);
        sum += vals[i];
    }
    red[t] = sum; __syncthreads();
    #pragma unroll
    for (int s2 = 128; s2 > 0; s2 >>= 1) {
        if (t < s2) red[t] += red[t + s2];
        __syncthreads();
    }
    const float inv = 1.0f / red[0];

    n = 0;
    for (int i = t; i < len; i += 256) r[i] = vals[n++] * inv;
}

// ---------------------------------------------------------------------------
// Kernel 4: context = P @ V per batch; causal -> k-loop stops at q-block end.
// ---------------------------------------------------------------------------
__global__ __launch_bounds__(256) void context_kernel(
    const float* __restrict__ P, float* __restrict__ OutAll)
{
    const int b  = blockIdx.z;
    const int q0 = blockIdx.y * 64;
    const int n0 = blockIdx.x * 64;
    const int tid = threadIdx.x;
    const int tx  = tid & 15;
    const int ty  = tid >> 4;

    const float* Pb = P   + (size_t)b * Ss * Ss;
    const float* V  = g_V + (size_t)b * Ss * Dd;
    float*       Ob = OutAll + (size_t)b * Ss * Dd;

    __shared__ float Ps[16][64];   // [k][q]
    __shared__ float Vs[16][64];   // [k][n]

    float acc[4][4] = {};
    const int kmax = q0 + 64;      // rows beyond the diagonal block are all zero

    for (int k0 = 0; k0 < kmax; k0 += 16) {
        {
            const int r  = tid >> 2;
            const int c4 = (tid & 3) * 4;
            float4 v = *(const float4*)&Pb[(size_t)(q0 + r) * Ss + k0 + c4];
            Ps[c4 + 0][r] = v.x; Ps[c4 + 1][r] = v.y;
            Ps[c4 + 2][r] = v.z; Ps[c4 + 3][r] = v.w;
        }
        {
            const int r  = tid >> 4;
            const int c4 = (tid & 15) * 4;
            *(float4*)&Vs[r][c4] = *(const float4*)&V[(size_t)(k0 + r) * Dd + n0 + c4];
        }
        __syncthreads();

        #pragma unroll
        for (int kk = 0; kk < 16; kk++) {
            float4 av = *(const float4*)&Ps[kk][ty * 4];
            float4 bv = *(const float4*)&Vs[kk][tx * 4];
            float a[4] = {av.x, av.y, av.z, av.w};
            float b2[4] = {bv.x, bv.y, bv.z, bv.w};
            #pragma unroll
            for (int i = 0; i < 4; i++)
                #pragma unroll
                for (int j = 0; j < 4; j++)
                    acc[i][j] += a[i] * b2[j];
        }
        __syncthreads();
    }

    #pragma unroll
    for (int i = 0; i < 4; i++) {
        const int q = q0 + ty * 4 + i;
        float4 v = {acc[i][0], acc[i][1], acc[i][2], acc[i][3]};
        *(float4*)&Ob[(size_t)q * Dd + n0 + tx * 4] = v;
    }
}

// ---------------------------------------------------------------------------
extern "C" void kernel_launch(void* const* d_in, const int* in_sizes, int n_in,
                              void* d_out, int out_size)
{
    const float* x  = (const float*)d_in[0];
    const float* Wq = (const float*)d_in[1];
    const float* Wk = (const float*)d_in[2];
    const float* Wv = (const float*)d_in[3];

    float* out = (float*)d_out;
    float* ctx = out;                                   // [4,2048,1024]
    float* sc  = out + (size_t)Bb * Ss * Dd;            // [4,2048,2048]

    // 1) QKV projection into device scratch
    qkv_kernel<<<dim3(3 * Dd / 64, BSs / 64), 256>>>(x, Wq, Wk, Wv);

    // 2) masked scaled scores
    scores_kernel<<<dim3(Ss / 64, Ss / 64, Bb), 256>>>(sc);

    // 3) causal softmax (in place)
    softmax_kernel<<<BSs, 256>>>(sc);

    // 4) context = P @ V
    context_kernel<<<dim3(Dd / 64, Ss / 64, Bb), 256>>>(sc, ctx);
}

// round 4
// speedup vs baseline: 2.1235x; 2.1235x over previous
#include <cuda_runtime.h>
#include <cuda_bf16.h>

// CausalAttention  B=4, S=2048, D=1024
// d_out = [ context (4*2048*1024 f32) | attn_scores (4*2048*2048 f32) ]

#define Bb   4
#define Ss   2048
#define Dd   1024
#define BSs  (Bb*Ss)

__device__ float g_Q[(size_t)BSs * Dd];
__device__ float g_K[(size_t)BSs * Dd];
__device__ float g_V[(size_t)BSs * Dd];

// 128x128 tile, BK=8, 256 threads, 8x8 reg tile, double-buffered smem.
#define PITCH 132
#define TSZ   (8 * PITCH)

__device__ __forceinline__ void mm_step(const float* __restrict__ As,
                                        const float* __restrict__ Bs,
                                        int ty, int tx, float acc[8][8])
{
    #pragma unroll
    for (int kk = 0; kk < 8; kk++) {
        float a[8], b[8];
        float4 a0 = *(const float4*)&As[kk * PITCH + ty * 4];
        float4 a1 = *(const float4*)&As[kk * PITCH + 64 + ty * 4];
        float4 b0 = *(const float4*)&Bs[kk * PITCH + tx * 4];
        float4 b1 = *(const float4*)&Bs[kk * PITCH + 64 + tx * 4];
        a[0]=a0.x; a[1]=a0.y; a[2]=a0.z; a[3]=a0.w;
        a[4]=a1.x; a[5]=a1.y; a[6]=a1.z; a[7]=a1.w;
        b[0]=b0.x; b[1]=b0.y; b[2]=b0.z; b[3]=b0.w;
        b[4]=b1.x; b[5]=b1.y; b[6]=b1.z; b[7]=b1.w;
        #pragma unroll
        for (int i = 0; i < 8; i++)
            #pragma unroll
            for (int j = 0; j < 8; j++)
                acc[i][j] += a[i] * b[j];
    }
}

// ---------------------------------------------------------------------------
// Kernel 1: QKV projection (A transposed into smem, B direct).
// ---------------------------------------------------------------------------
__global__ __launch_bounds__(256, 2) void qkv_kernel(
    const float* __restrict__ X,
    const float* __restrict__ Wq,
    const float* __restrict__ Wk,
    const float* __restrict__ Wv)
{
    __shared__ float As[2][TSZ];
    __shared__ float Bs[2][TSZ];

    const int m0   = blockIdx.y * 128;
    const int widx = blockIdx.x >> 3;
    const int col0 = (blockIdx.x & 7) * 128;

    const float* W   = (widx == 0) ? Wq : (widx == 1) ? Wk : Wv;
    float*       Out = (widx == 0) ? g_Q : (widx == 1) ? g_K : g_V;

    const int tid = threadIdx.x;
    const int tx  = tid & 15;
    const int ty  = tid >> 4;
    const int ra  = tid >> 1;            // 0..127
    const int ca  = (tid & 1) * 4;       // 0 or 4
    const int rb  = tid >> 5;            // 0..7
    const int cb  = (tid & 31) * 4;      // 0..124

    const float* pA = &X[(size_t)(m0 + ra) * Dd + ca];
    const float* pB = &W[(size_t)rb * Dd + col0 + cb];

    float acc[8][8] = {};

    // preload block 0
    {
        float4 av = *(const float4*)pA;
        float4 bv = *(const float4*)pB;
        As[0][(ca + 0) * PITCH + ra] = av.x;
        As[0][(ca + 1) * PITCH + ra] = av.y;
        As[0][(ca + 2) * PITCH + ra] = av.z;
        As[0][(ca + 3) * PITCH + ra] = av.w;
        *(float4*)&Bs[0][rb * PITCH + cb] = bv;
    }
    __syncthreads();

    int buf = 0;
    const int NB = Dd / 8;   // 128
    for (int kb = 0; kb < NB; kb++) {
        float4 av, bv;
        const bool next = (kb + 1 < NB);
        if (next) {
            av = *(const float4*)(pA + (kb + 1) * 8);
            bv = *(const float4*)(pB + (size_t)(kb + 1) * 8 * Dd);
        }
        mm_step(As[buf], Bs[buf], ty, tx, acc);
        if (next) {
            const int nb = buf ^ 1;
            As[nb][(ca + 0) * PITCH + ra] = av.x;
            As[nb][(ca + 1) * PITCH + ra] = av.y;
            As[nb][(ca + 2) * PITCH + ra] = av.z;
            As[nb][(ca + 3) * PITCH + ra] = av.w;
            *(float4*)&Bs[nb][rb * PITCH + cb] = bv;
        }
        __syncthreads();
        buf ^= 1;
    }

    #pragma unroll
    for (int ih = 0; ih < 2; ih++)
        #pragma unroll
        for (int i = 0; i < 4; i++) {
            const int m = m0 + ih * 64 + ty * 4 + i;
            #pragma unroll
            for (int jh = 0; jh < 2; jh++) {
                float4 v = {acc[ih*4+i][jh*4+0], acc[ih*4+i][jh*4+1],
                            acc[ih*4+i][jh*4+2], acc[ih*4+i][jh*4+3]};
                *(float4*)&Out[(size_t)m * Dd + col0 + jh * 64 + tx * 4] = v;
            }
        }
}

// ---------------------------------------------------------------------------
// Kernel 2: masked scaled scores (both operands transposed into smem).
// ---------------------------------------------------------------------------
__global__ __launch_bounds__(256, 2) void scores_kernel(float* __restrict__ Sout)
{
    const int b  = blockIdx.z;
    const int q0 = blockIdx.y * 128;
    const int k0 = blockIdx.x * 128;
    const int tid = threadIdx.x;

    float* Sb = Sout + (size_t)b * Ss * Ss;

    if (k0 > q0 + 127) {                  // fully masked: zero-fill
        const float4 z = {0.f, 0.f, 0.f, 0.f};
        #pragma unroll
        for (int it = 0; it < 16; it++) {
            const int idx = it * 256 + tid;
            const int r = idx >> 5;
            const int c = (idx & 31) * 4;
            *(float4*)&Sb[(size_t)(q0 + r) * Ss + k0 + c] = z;
        }
        return;
    }

    __shared__ float As[2][TSZ];
    __shared__ float Bs[2][TSZ];

    const float* Q = g_Q + (size_t)b * Ss * Dd;
    const float* K = g_K + (size_t)b * Ss * Dd;

    const int tx  = tid & 15;
    const int ty  = tid >> 4;
    const int ra  = tid >> 1;
    const int ca  = (tid & 1) * 4;

    const float* pA = &Q[(size_t)(q0 + ra) * Dd + ca];
    const float* pB = &K[(size_t)(k0 + ra) * Dd + ca];

    float acc[8][8] = {};

    {
        float4 av = *(const float4*)pA;
        float4 bv = *(const float4*)pB;
        As[0][(ca + 0) * PITCH + ra] = av.x;
        As[0][(ca + 1) * PITCH + ra] = av.y;
        As[0][(ca + 2) * PITCH + ra] = av.z;
        As[0][(ca + 3) * PITCH + ra] = av.w;
        Bs[0][(ca + 0) * PITCH + ra] = bv.x;
        Bs[0][(ca + 1) * PITCH + ra] = bv.y;
        Bs[0][(ca + 2) * PITCH + ra] = bv.z;
        Bs[0][(ca + 3) * PITCH + ra] = bv.w;
    }
    __syncthreads();

    int buf = 0;
    const int NB = Dd / 8;
    for (int kb = 0; kb < NB; kb++) {
        float4 av, bv;
        const bool next = (kb + 1 < NB);
        if (next) {
            av = *(const float4*)(pA + (kb + 1) * 8);
            bv = *(const float4*)(pB + (kb + 1) * 8);
        }
        mm_step(As[buf], Bs[buf], ty, tx, acc);
        if (next) {
            const int nb = buf ^ 1;
            As[nb][(ca + 0) * PITCH + ra] = av.x;
            As[nb][(ca + 1) * PITCH + ra] = av.y;
            As[nb][(ca + 2) * PITCH + ra] = av.z;
            As[nb][(ca + 3) * PITCH + ra] = av.w;
            Bs[nb][(ca + 0) * PITCH + ra] = bv.x;
            Bs[nb][(ca + 1) * PITCH + ra] = bv.y;
            Bs[nb][(ca + 2) * PITCH + ra] = bv.z;
            Bs[nb][(ca + 3) * PITCH + ra] = bv.w;
        }
        __syncthreads();
        buf ^= 1;
    }

    const float scale = 0.03125f;   // 1/sqrt(1024)
    #pragma unroll
    for (int ih = 0; ih < 2; ih++)
        #pragma unroll
        for (int i = 0; i < 4; i++) {
            const int q = q0 + ih * 64 + ty * 4 + i;
            #pragma unroll
            for (int jh = 0; jh < 2; jh++) {
                const int kbase = k0 + jh * 64 + tx * 4;
                float4 v;
                v.x = (kbase + 0 <= q) ? acc[ih*4+i][jh*4+0] * scale : 0.f;
                v.y = (kbase + 1 <= q) ? acc[ih*4+i][jh*4+1] * scale : 0.f;
                v.z = (kbase + 2 <= q) ? acc[ih*4+i][jh*4+2] * scale : 0.f;
                v.w = (kbase + 3 <= q) ? acc[ih*4+i][jh*4+3] * scale : 0.f;
                *(float4*)&Sb[(size_t)q * Ss + kbase] = v;
            }
        }
}

// ---------------------------------------------------------------------------
// Kernel 3: causal row softmax, in place.
// ---------------------------------------------------------------------------
__global__ __launch_bounds__(256) void softmax_kernel(float* __restrict__ Sc)
{
    const int row = blockIdx.x;
    const int b = row / Ss;
    const int q = row - b * Ss;
    float* r = Sc + (size_t)b * Ss * Ss + (size_t)q * Ss;
    const int len = q + 1;
    const int t = threadIdx.x;

    __shared__ float red[256];

    float vals[8];
    int   n = 0;
    float m = -3.4e38f;
    for (int i = t; i < len; i += 256) {
        float v = r[i];
        vals[n++] = v;
        m = fmaxf(m, v);
    }
    red[t] = m; __syncthreads();
    #pragma unroll
    for (int s2 = 128; s2 > 0; s2 >>= 1) {
        if (t < s2) red[t] = fmaxf(red[t], red[t + s2]);
        __syncthreads();
    }
    m = red[0]; __syncthreads();

    float sum = 0.f;
    for (int i = 0; i < n; i++) {
        vals[i] = __expf(vals[i] - m);
        sum += vals[i];
    }
    red[t] = sum; __syncthreads();
    #pragma unroll
    for (int s2 = 128; s2 > 0; s2 >>= 1) {
        if (t < s2) red[t] += red[t + s2];
        __syncthreads();
    }
    const float inv = 1.0f / red[0];

    n = 0;
    for (int i = t; i < len; i += 256) r[i] = vals[n++] * inv;
}

// ---------------------------------------------------------------------------
// Kernel 4: context = P @ V, k-loop stops after the diagonal q-block.
// ---------------------------------------------------------------------------
__global__ __launch_bounds__(256, 2) void context_kernel(
    const float* __restrict__ P, float* __restrict__ OutAll)
{
    const int b  = blockIdx.z;
    const int q0 = blockIdx.y * 128;
    const int n0 = blockIdx.x * 128;
    const int tid = threadIdx.x;
    const int tx  = tid & 15;
    const int ty  = tid >> 4;

    const float* Pb = P   + (size_t)b * Ss * Ss;
    const float* V  = g_V + (size_t)b * Ss * Dd;
    float*       Ob = OutAll + (size_t)b * Ss * Dd;

    __shared__ float As[2][TSZ];
    __shared__ float Bs[2][TSZ];

    const int ra  = tid >> 1;
    const int ca  = (tid & 1) * 4;
    const int rb  = tid >> 5;
    const int cb  = (tid & 31) * 4;

    const float* pA = &Pb[(size_t)(q0 + ra) * Ss + ca];
    const float* pB = &V[(size_t)rb * Dd + n0 + cb];

    float acc[8][8] = {};
    const int NB = (q0 + 128) / 8;   // causal: P is zero past diagonal block

    {
        float4 av = *(const float4*)pA;
        float4 bv = *(const float4*)pB;
        As[0][(ca + 0) * PITCH + ra] = av.x;
        As[0][(ca + 1) * PITCH + ra] = av.y;
        As[0][(ca + 2) * PITCH + ra] = av.z;
        As[0][(ca + 3) * PITCH + ra] = av.w;
        *(float4*)&Bs[0][rb * PITCH + cb] = bv;
    }
    __syncthreads();

    int buf = 0;
    for (int kb = 0; kb < NB; kb++) {
        float4 av, bv;
        const bool next = (kb + 1 < NB);
        if (next) {
            av = *(const float4*)(pA + (kb + 1) * 8);
            bv = *(const float4*)(pB + (size_t)(kb + 1) * 8 * Dd);
        }
        mm_step(As[buf], Bs[buf], ty, tx, acc);
        if (next) {
            const int nb = buf ^ 1;
            As[nb][(ca + 0) * PITCH + ra] = av.x;
            As[nb][(ca + 1) * PITCH + ra] = av.y;
            As[nb][(ca + 2) * PITCH + ra] = av.z;
            As[nb][(ca + 3) * PITCH + ra] = av.w;
            *(float4*)&Bs[nb][rb * PITCH + cb] = bv;
        }
        __syncthreads();
        buf ^= 1;
    }

    #pragma unroll
    for (int ih = 0; ih < 2; ih++)
        #pragma unroll
        for (int i = 0; i < 4; i++) {
            const int q = q0 + ih * 64 + ty * 4 + i;
            #pragma unroll
            for (int jh = 0; jh < 2; jh++) {
                float4 v = {acc[ih*4+i][jh*4+0], acc[ih*4+i][jh*4+1],
                            acc[ih*4+i][jh*4+2], acc[ih*4+i][jh*4+3]};
                *(float4*)&Ob[(size_t)q * Dd + n0 + jh * 64 + tx * 4] = v;
            }
        }
}

// ---------------------------------------------------------------------------
extern "C" void kernel_launch(void* const* d_in, const int* in_sizes, int n_in,
                              void* d_out, int out_size)
{
    const float* x  = (const float*)d_in[0];
    const float* Wq = (const float*)d_in[1];
    const float* Wk = (const float*)d_in[2];
    const float* Wv = (const float*)d_in[3];

    float* out = (float*)d_out;
    float* ctx = out;
    float* sc  = out + (size_t)Bb * Ss * Dd;

    qkv_kernel<<<dim3(24, BSs / 128), 256>>>(x, Wq, Wk, Wv);
    scores_kernel<<<dim3(Ss / 128, Ss / 128, Bb), 256>>>(sc);
    softmax_kernel<<<BSs, 256>>>(sc);
    context_kernel<<<dim3(Dd / 128, Ss / 128, Bb), 256>>>(sc, ctx);
}

// round 9
// speedup vs baseline: 3.1580x; 1.4872x over previous
#include <cuda_runtime.h>
#include <cuda_fp16.h>
#include <cstdint>

// CausalAttention B=4, S=2048, D=1024 — mma.sync (HMMA) fp16x2 emulated-fp32
// d_out = [ context (4*2048*1024 f32) | attn_scores (4*2048*2048 f32) ]
// Static 40KB smem, single buffer + register prefetch (no cudaFuncSetAttribute,
// no dynamic smem — minimal launch-path surface).

#define Bb 4
#define Ss 2048
#define Dd 1024
#define BSs (Bb*Ss)

__device__ float g_Q[(size_t)BSs * Dd];
__device__ float g_K[(size_t)BSs * Dd];
__device__ float g_V[(size_t)BSs * Dd];

// 128x128 tile, BK=32, 256 threads (8 warps, 64x32 warp tiles)
#define BM 128
#define BN 128
#define BK 32
#define KPAD 40                        // halves per smem row (32 data + 8 pad)
#define PLANEH (BM * KPAD)             // 5120 halves
// planes: A0, A1, B0, B1  -> 4*5120*2 = 40960 B static shared

__device__ __forceinline__ uint32_t smem_u32(const void* p) {
    uint32_t a;
    asm("{ .reg .u64 t; cvta.to.shared.u64 t, %1; cvt.u32.u64 %0, t; }" : "=r"(a) : "l"(p));
    return a;
}

__device__ __forceinline__ void ldsm_x4(uint32_t* a, uint32_t addr) {
    asm volatile("ldmatrix.sync.aligned.m8n8.x4.shared.b16 {%0,%1,%2,%3}, [%4];"
                 : "=r"(a[0]), "=r"(a[1]), "=r"(a[2]), "=r"(a[3]) : "r"(addr));
}

__device__ __forceinline__ void mma16816(float* d, const uint32_t* a, const uint32_t* b) {
    asm volatile(
        "mma.sync.aligned.m16n8k16.row.col.f32.f16.f16.f32 "
        "{%0,%1,%2,%3}, {%4,%5,%6,%7}, {%8,%9}, {%0,%1,%2,%3};"
        : "+f"(d[0]), "+f"(d[1]), "+f"(d[2]), "+f"(d[3])
        : "r"(a[0]), "r"(a[1]), "r"(a[2]), "r"(a[3]), "r"(b[0]), "r"(b[1]));
}

__device__ __forceinline__ void split2(float v, __half& h0, __half& h1) {
    h0 = __float2half_rn(v);
    h1 = __float2half_rn(v - __half2float(h0));
}

// ---------------------------------------------------------------------------
// Core: C(128x128) += A(128xK) . B^T, smem B holds [n][k].
// BT=false: B source [n][ldb] (k contiguous)  -> direct stage
// BT=true : B source [k][ldb] (n contiguous)  -> transposed stage
// sm layout (halves): A0 | A1 | B0 | B1, each PLANEH
// ---------------------------------------------------------------------------
template <bool BT>
__device__ __forceinline__ void mma_gemm(__half* sm,
                                         const float* __restrict__ A, size_t lda,
                                         const float* __restrict__ B, size_t ldb,
                                         int NB, float acc[4][4][4])
{
    const int tid  = threadIdx.x;
    const int lane = tid & 31;
    const int wid  = tid >> 5;
    const int wm   = (wid & 1) * 64;
    const int wn   = (wid >> 1) * 32;

    const int rA  = tid >> 3;            // 0..31 (+32 per it)
    const int cA  = (tid & 7) * 4;
    const int ncB = tid & 127;
    const int hkB = tid >> 7;            // 0/1

    __half* a0 = sm;
    __half* a1 = sm + PLANEH;
    __half* b0 = sm + 2 * PLANEH;
    __half* b1 = sm + 3 * PLANEH;

    float4 pfA[4];
    float4 pfBd[4];
    float  pfBt[4][4];

    // prefetch chunk 0
    #pragma unroll
    for (int it = 0; it < 4; it++)
        pfA[it] = *(const float4*)&A[(size_t)(rA + it*32) * lda + cA];
    if (!BT) {
        #pragma unroll
        for (int it = 0; it < 4; it++)
            pfBd[it] = *(const float4*)&B[(size_t)(rA + it*32) * ldb + cA];
    } else {
        #pragma unroll
        for (int it = 0; it < 4; it++) {
            const int kr = (it*2 + hkB) * 4;
            #pragma unroll
            for (int j = 0; j < 4; j++)
                pfBt[it][j] = B[(size_t)(kr + j) * ldb + ncB];
        }
    }

    for (int c = 0; c < NB; c++) {
        // ---- store prefetched chunk into smem ----
        #pragma unroll
        for (int it = 0; it < 4; it++) {
            const int r = rA + it*32;
            const float v[4] = {pfA[it].x, pfA[it].y, pfA[it].z, pfA[it].w};
            #pragma unroll
            for (int j = 0; j < 4; j++) {
                __half h0, h1; split2(v[j], h0, h1);
                a0[r*KPAD + cA + j] = h0; a1[r*KPAD + cA + j] = h1;
            }
        }
        if (!BT) {
            #pragma unroll
            for (int it = 0; it < 4; it++) {
                const int r = rA + it*32;
                const float v[4] = {pfBd[it].x, pfBd[it].y, pfBd[it].z, pfBd[it].w};
                #pragma unroll
                for (int j = 0; j < 4; j++) {
                    __half h0, h1; split2(v[j], h0, h1);
                    b0[r*KPAD + cA + j] = h0; b1[r*KPAD + cA + j] = h1;
                }
            }
        } else {
            #pragma unroll
            for (int it = 0; it < 4; it++) {
                const int kr = (it*2 + hkB) * 4;
                #pragma unroll
                for (int j = 0; j < 4; j++) {
                    __half h0, h1; split2(pfBt[it][j], h0, h1);
                    b0[ncB*KPAD + kr + j] = h0; b1[ncB*KPAD + kr + j] = h1;
                }
            }
        }
        __syncthreads();

        // ---- prefetch chunk c+1 (overlaps with compute below) ----
        const bool next = (c + 1 < NB);
        if (next) {
            const size_t ko = (size_t)(c + 1) * BK;
            #pragma unroll
            for (int it = 0; it < 4; it++)
                pfA[it] = *(const float4*)&A[(size_t)(rA + it*32) * lda + ko + cA];
            if (!BT) {
                #pragma unroll
                for (int it = 0; it < 4; it++)
                    pfBd[it] = *(const float4*)&B[(size_t)(rA + it*32) * ldb + ko + cA];
            } else {
                #pragma unroll
                for (int it = 0; it < 4; it++) {
                    const int kr = (it*2 + hkB) * 4;
                    #pragma unroll
                    for (int j = 0; j < 4; j++)
                        pfBt[it][j] = B[(ko + kr + j) * ldb + ncB];
                }
            }
        }

        // ---- compute on smem ----
        {
            const uint32_t aB0 = smem_u32(a0);
            const uint32_t aB1 = smem_u32(a1);
            #pragma unroll
            for (int ks = 0; ks < 2; ks++) {
                uint32_t afr[2][4][4];
                const int arow = wm + (lane & 15);
                const int acol = ks*16 + (lane >> 4) * 8;
                #pragma unroll
                for (int im = 0; im < 4; im++) {
                    ldsm_x4(afr[0][im], aB0 + (uint32_t)((arow + im*16)*KPAD + acol)*2);
                    ldsm_x4(afr[1][im], aB1 + (uint32_t)((arow + im*16)*KPAD + acol)*2);
                }
                uint32_t bfr[2][4][2];
                const int bn = wn + (lane >> 2);
                const int bk = ks*16 + (lane & 3)*2;
                #pragma unroll
                for (int in_ = 0; in_ < 4; in_++) {
                    const __half* p0 = b0 + (bn + in_*8)*KPAD + bk;
                    const __half* p1 = b1 + (bn + in_*8)*KPAD + bk;
                    bfr[0][in_][0] = *(const uint32_t*)p0;
                    bfr[0][in_][1] = *(const uint32_t*)(p0 + 8);
                    bfr[1][in_][0] = *(const uint32_t*)p1;
                    bfr[1][in_][1] = *(const uint32_t*)(p1 + 8);
                }
                #pragma unroll
                for (int im = 0; im < 4; im++)
                    #pragma unroll
                    for (int in_ = 0; in_ < 4; in_++) {
                        mma16816(acc[im][in_], afr[0][im], bfr[0][in_]);  // a0*b0
                        mma16816(acc[im][in_], afr[1][im], bfr[0][in_]);  // a1*b0
                        mma16816(acc[im][in_], afr[0][im], bfr[1][in_]);  // a0*b1
                    }
            }
        }
        __syncthreads();   // smem reuse next iteration
    }
}

// ---------------------------------------------------------------------------
// Kernel 1: QKV projection.
// ---------------------------------------------------------------------------
__global__ __launch_bounds__(256) void qkv_mma(
    const float* __restrict__ X,
    const float* __restrict__ Wq,
    const float* __restrict__ Wk,
    const float* __restrict__ Wv)
{
    __shared__ __half sm[4 * PLANEH];

    const int n0g  = blockIdx.x * BN;
    const int m0   = blockIdx.y * BM;
    const int widx = n0g >> 10;
    const int col0 = n0g & 1023;

    const float* W   = (widx == 0) ? Wq : (widx == 1) ? Wk : Wv;
    float*       Out = (widx == 0) ? g_Q : (widx == 1) ? g_K : g_V;

    float acc[4][4][4] = {};
    mma_gemm<true>(sm, X + (size_t)m0 * Dd, Dd, W + col0, Dd, Dd / BK, acc);

    const int lane = threadIdx.x & 31, wid = threadIdx.x >> 5;
    const int wm = (wid & 1) * 64, wn = (wid >> 1) * 32;
    #pragma unroll
    for (int im = 0; im < 4; im++)
        #pragma unroll
        for (int in_ = 0; in_ < 4; in_++) {
            const int r0 = m0 + wm + im*16 + (lane >> 2);
            const int c0 = col0 + wn + in_*8 + (lane & 3)*2;
            float2 v0 = {acc[im][in_][0], acc[im][in_][1]};
            float2 v1 = {acc[im][in_][2], acc[im][in_][3]};
            *(float2*)&Out[(size_t)r0 * Dd + c0]       = v0;
            *(float2*)&Out[(size_t)(r0 + 8) * Dd + c0] = v1;
        }
}

// ---------------------------------------------------------------------------
// Kernel 2: scores = (Q.K^T)/32, causal masked.
// ---------------------------------------------------------------------------
__global__ __launch_bounds__(256) void scores_mma(float* __restrict__ Sout)
{
    __shared__ __half sm[4 * PLANEH];

    const int b  = blockIdx.z;
    const int q0 = blockIdx.y * BM;
    const int k0 = blockIdx.x * BN;
    const int tid = threadIdx.x;
    float* Sb = Sout + (size_t)b * Ss * Ss;

    if (k0 > q0 + 127) {                       // fully masked tile
        const float4 z = {0.f, 0.f, 0.f, 0.f};
        for (int t = tid; t < 4096; t += 256) {
            const int r = t >> 5, c4 = (t & 31) * 4;
            *(float4*)&Sb[(size_t)(q0 + r) * Ss + k0 + c4] = z;
        }
        return;
    }

    float acc[4][4][4] = {};
    mma_gemm<false>(sm,
        g_Q + ((size_t)b * Ss + q0) * Dd, Dd,
        g_K + ((size_t)b * Ss + k0) * Dd, Dd,
        Dd / BK, acc);

    const float scale = 0.03125f;
    const int lane = tid & 31, wid = tid >> 5;
    const int wm = (wid & 1) * 64, wn = (wid >> 1) * 32;
    #pragma unroll
    for (int im = 0; im < 4; im++)
        #pragma unroll
        for (int in_ = 0; in_ < 4; in_++) {
            const int q  = q0 + wm + im*16 + (lane >> 2);
            const int kk = k0 + wn + in_*8 + (lane & 3)*2;
            float2 v0, v1;
            v0.x = (kk   <= q)     ? acc[im][in_][0] * scale : 0.f;
            v0.y = (kk+1 <= q)     ? acc[im][in_][1] * scale : 0.f;
            v1.x = (kk   <= q + 8) ? acc[im][in_][2] * scale : 0.f;
            v1.y = (kk+1 <= q + 8) ? acc[im][in_][3] * scale : 0.f;
            *(float2*)&Sb[(size_t)q * Ss + kk]       = v0;
            *(float2*)&Sb[(size_t)(q + 8) * Ss + kk] = v1;
        }
}

// ---------------------------------------------------------------------------
// Kernel 3: causal row softmax, in place.
// ---------------------------------------------------------------------------
__global__ __launch_bounds__(256) void softmax_kernel(float* __restrict__ Sc)
{
    const int row = blockIdx.x;
    const int b = row / Ss;
    const int q = row - b * Ss;
    float* r = Sc + (size_t)b * Ss * Ss + (size_t)q * Ss;
    const int len = q + 1;
    const int t = threadIdx.x;

    __shared__ float red[256];

    float vals[8];
    int n = 0;
    float m = -3.4e38f;
    for (int i = t; i < len; i += 256) { float v = r[i]; vals[n++] = v; m = fmaxf(m, v); }
    red[t] = m; __syncthreads();
    #pragma unroll
    for (int s2 = 128; s2 > 0; s2 >>= 1) {
        if (t < s2) red[t] = fmaxf(red[t], red[t + s2]);
        __syncthreads();
    }
    m = red[0]; __syncthreads();

    float sum = 0.f;
    for (int i = 0; i < n; i++) { vals[i] = __expf(vals[i] - m); sum += vals[i]; }
    red[t] = sum; __syncthreads();
    #pragma unroll
    for (int s2 = 128; s2 > 0; s2 >>= 1) {
        if (t < s2) red[t] += red[t + s2];
        __syncthreads();
    }
    const float inv = 1.0f / red[0];

    n = 0;
    for (int i = t; i < len; i += 256) r[i] = vals[n++] * inv;
}

// ---------------------------------------------------------------------------
// Kernel 4: context = P @ V  (K loop stops past diagonal q-block).
// ---------------------------------------------------------------------------
__global__ __launch_bounds__(256) void context_mma(
    const float* __restrict__ P, float* __restrict__ Ctx)
{
    __shared__ __half sm[4 * PLANEH];

    const int b  = blockIdx.z;
    const int q0 = blockIdx.y * BM;
    const int n0 = blockIdx.x * BN;

    float acc[4][4][4] = {};
    mma_gemm<true>(sm,
        P + (size_t)b * Ss * Ss + (size_t)q0 * Ss, Ss,
        g_V + (size_t)b * Ss * Dd + n0, Dd,
        q0 / BK + 4, acc);

    float* Ob = Ctx + (size_t)b * Ss * Dd;
    const int lane = threadIdx.x & 31, wid = threadIdx.x >> 5;
    const int wm = (wid & 1) * 64, wn = (wid >> 1) * 32;
    #pragma unroll
    for (int im = 0; im < 4; im++)
        #pragma unroll
        for (int in_ = 0; in_ < 4; in_++) {
            const int r0 = q0 + wm + im*16 + (lane >> 2);
            const int c0 = n0 + wn + in_*8 + (lane & 3)*2;
            float2 v0 = {acc[im][in_][0], acc[im][in_][1]};
            float2 v1 = {acc[im][in_][2], acc[im][in_][3]};
            *(float2*)&Ob[(size_t)r0 * Dd + c0]       = v0;
            *(float2*)&Ob[(size_t)(r0 + 8) * Dd + c0] = v1;
        }
}

// ---------------------------------------------------------------------------
extern "C" void kernel_launch(void* const* d_in, const int* in_sizes, int n_in,
                              void* d_out, int out_size)
{
    const float* x  = (const float*)d_in[0];
    const float* Wq = (const float*)d_in[1];
    const float* Wk = (const float*)d_in[2];
    const float* Wv = (const float*)d_in[3];

    float* out = (float*)d_out;
    float* ctx = out;
    float* sc  = out + (size_t)Bb * Ss * Dd;

    qkv_mma<<<dim3(3 * Dd / BN, BSs / BM), 256>>>(x, Wq, Wk, Wv);
    scores_mma<<<dim3(Ss / BN, Ss / BM, Bb), 256>>>(sc);
    softmax_kernel<<<BSs, 256>>>(sc);
    context_mma<<<dim3(Dd / BN, Ss / BM, Bb), 256>>>(sc, ctx);
}

// round 10
// speedup vs baseline: 4.3754x; 1.3855x over previous
#include <cuda_runtime.h>
#include <cuda_fp16.h>
#include <cstdint>

// CausalAttention B=4, S=2048, D=1024 — mma.sync (HMMA) fp16x2 emulated-fp32
// d_out = [ context (4*2048*1024 f32) | attn_scores (4*2048*2048 f32) ]
// Double-buffered smem (80KB dynamic): stage c+1 overlaps compute on c.

#define Bb 4
#define Ss 2048
#define Dd 1024
#define BSs (Bb*Ss)

__device__ float g_Q[(size_t)BSs * Dd];
__device__ float g_K[(size_t)BSs * Dd];
__device__ float g_V[(size_t)BSs * Dd];

// 128x128 tile, BK=32, 256 threads (8 warps, 64x32 warp tiles)
#define BM 128
#define BN 128
#define BK 32
#define KPAD 40                        // halves per smem row (32 data + 8 pad)
#define PLANEH (BM * KPAD)             // 5120 halves
#define SMEM_BYTES (2 * 4 * PLANEH * 2)   // 2 bufs x 4 planes = 81920 B

__device__ __forceinline__ uint32_t smem_u32(const void* p) {
    uint32_t a;
    asm("{ .reg .u64 t; cvta.to.shared.u64 t, %1; cvt.u32.u64 %0, t; }" : "=r"(a) : "l"(p));
    return a;
}

__device__ __forceinline__ void ldsm_x4(uint32_t* a, uint32_t addr) {
    asm volatile("ldmatrix.sync.aligned.m8n8.x4.shared.b16 {%0,%1,%2,%3}, [%4];"
                 : "=r"(a[0]), "=r"(a[1]), "=r"(a[2]), "=r"(a[3]) : "r"(addr));
}

__device__ __forceinline__ void mma16816(float* d, const uint32_t* a, const uint32_t* b) {
    asm volatile(
        "mma.sync.aligned.m16n8k16.row.col.f32.f16.f16.f32 "
        "{%0,%1,%2,%3}, {%4,%5,%6,%7}, {%8,%9}, {%0,%1,%2,%3};"
        : "+f"(d[0]), "+f"(d[1]), "+f"(d[2]), "+f"(d[3])
        : "r"(a[0]), "r"(a[1]), "r"(a[2]), "r"(a[3]), "r"(b[0]), "r"(b[1]));
}

__device__ __forceinline__ void split2(float v, __half& h0, __half& h1) {
    h0 = __float2half_rn(v);
    h1 = __float2half_rn(v - __half2float(h0));
}

// ---------------------------------------------------------------------------
// Core: C(128x128) += A(128xK) . B^T, smem B holds [n][k].
// BT=false: B source [n][ldb] (k contiguous)  -> direct stage
// BT=true : B source [k][ldb] (n contiguous)  -> transposed stage
// smem (halves): buf b -> planes A0|A1|B0|B1 at (b*4 + p)*PLANEH
// ---------------------------------------------------------------------------
template <bool BT>
__device__ __forceinline__ void mma_gemm(__half* sm,
                                         const float* __restrict__ A, size_t lda,
                                         const float* __restrict__ B, size_t ldb,
                                         int NB, float acc[4][4][4])
{
    const int tid  = threadIdx.x;
    const int lane = tid & 31;
    const int wid  = tid >> 5;
    const int wm   = (wid & 1) * 64;
    const int wn   = (wid >> 1) * 32;

    const int rA  = tid >> 3;            // 0..31 (+32 per it)
    const int cA  = (tid & 7) * 4;
    const int ncB = tid & 127;
    const int hkB = tid >> 7;            // 0/1

    float4 pfA[4];
    float4 pfBd[4];
    float  pfBt[4][4];

    // ---- helper lambdas (inlined) ----
    auto load_chunk = [&](int c) {
        const size_t ko = (size_t)c * BK;
        #pragma unroll
        for (int it = 0; it < 4; it++)
            pfA[it] = *(const float4*)&A[(size_t)(rA + it*32) * lda + ko + cA];
        if (!BT) {
            #pragma unroll
            for (int it = 0; it < 4; it++)
                pfBd[it] = *(const float4*)&B[(size_t)(rA + it*32) * ldb + ko + cA];
        } else {
            #pragma unroll
            for (int it = 0; it < 4; it++) {
                const int kr = (it*2 + hkB) * 4;
                #pragma unroll
                for (int j = 0; j < 4; j++)
                    pfBt[it][j] = B[(ko + kr + j) * ldb + ncB];
            }
        }
    };

    auto store_chunk = [&](int buf) {
        __half* a0 = sm + (size_t)(buf*4 + 0) * PLANEH;
        __half* a1 = sm + (size_t)(buf*4 + 1) * PLANEH;
        __half* b0 = sm + (size_t)(buf*4 + 2) * PLANEH;
        __half* b1 = sm + (size_t)(buf*4 + 3) * PLANEH;
        #pragma unroll
        for (int it = 0; it < 4; it++) {
            const int r = rA + it*32;
            const float v[4] = {pfA[it].x, pfA[it].y, pfA[it].z, pfA[it].w};
            #pragma unroll
            for (int j = 0; j < 4; j++) {
                __half h0, h1; split2(v[j], h0, h1);
                a0[r*KPAD + cA + j] = h0; a1[r*KPAD + cA + j] = h1;
            }
        }
        if (!BT) {
            #pragma unroll
            for (int it = 0; it < 4; it++) {
                const int r = rA + it*32;
                const float v[4] = {pfBd[it].x, pfBd[it].y, pfBd[it].z, pfBd[it].w};
                #pragma unroll
                for (int j = 0; j < 4; j++) {
                    __half h0, h1; split2(v[j], h0, h1);
                    b0[r*KPAD + cA + j] = h0; b1[r*KPAD + cA + j] = h1;
                }
            }
        } else {
            #pragma unroll
            for (int it = 0; it < 4; it++) {
                const int kr = (it*2 + hkB) * 4;
                #pragma unroll
                for (int j = 0; j < 4; j++) {
                    __half h0, h1; split2(pfBt[it][j], h0, h1);
                    b0[ncB*KPAD + kr + j] = h0; b1[ncB*KPAD + kr + j] = h1;
                }
            }
        }
    };

    // prologue: chunk 0 into buffer 0
    load_chunk(0);
    store_chunk(0);
    __syncthreads();

    for (int c = 0; c < NB; c++) {
        const int buf = c & 1;
        const bool next = (c + 1 < NB);
        if (next) load_chunk(c + 1);          // gmem loads issue early

        // ---- compute on buf ----
        {
            __half* a0 = sm + (size_t)(buf*4 + 0) * PLANEH;
            __half* a1 = sm + (size_t)(buf*4 + 1) * PLANEH;
            __half* b0 = sm + (size_t)(buf*4 + 2) * PLANEH;
            __half* b1 = sm + (size_t)(buf*4 + 3) * PLANEH;
            const uint32_t aB0 = smem_u32(a0);
            const uint32_t aB1 = smem_u32(a1);
            #pragma unroll
            for (int ks = 0; ks < 2; ks++) {
                uint32_t afr[2][4][4];
                const int arow = wm + (lane & 15);
                const int acol = ks*16 + (lane >> 4) * 8;
                #pragma unroll
                for (int im = 0; im < 4; im++) {
                    ldsm_x4(afr[0][im], aB0 + (uint32_t)((arow + im*16)*KPAD + acol)*2);
                    ldsm_x4(afr[1][im], aB1 + (uint32_t)((arow + im*16)*KPAD + acol)*2);
                }
                uint32_t bfr[2][4][2];
                const int bn = wn + (lane >> 2);
                const int bk = ks*16 + (lane & 3)*2;
                #pragma unroll
                for (int in_ = 0; in_ < 4; in_++) {
                    const __half* p0 = b0 + (bn + in_*8)*KPAD + bk;
                    const __half* p1 = b1 + (bn + in_*8)*KPAD + bk;
                    bfr[0][in_][0] = *(const uint32_t*)p0;
                    bfr[0][in_][1] = *(const uint32_t*)(p0 + 8);
                    bfr[1][in_][0] = *(const uint32_t*)p1;
                    bfr[1][in_][1] = *(const uint32_t*)(p1 + 8);
                }
                #pragma unroll
                for (int im = 0; im < 4; im++)
                    #pragma unroll
                    for (int in_ = 0; in_ < 4; in_++) {
                        mma16816(acc[im][in_], afr[0][im], bfr[0][in_]);  // a0*b0
                        mma16816(acc[im][in_], afr[1][im], bfr[0][in_]);  // a1*b0
                        mma16816(acc[im][in_], afr[0][im], bfr[1][in_]);  // a0*b1
                    }
            }
        }

        // ---- store c+1 into the other buffer (safe: last read of it ended
        //      before the previous __syncthreads) ----
        if (next) store_chunk(buf ^ 1);
        __syncthreads();
    }
}

// ---------------------------------------------------------------------------
// Kernel 1: QKV projection.
// ---------------------------------------------------------------------------
__global__ __launch_bounds__(256) void qkv_mma(
    const float* __restrict__ X,
    const float* __restrict__ Wq,
    const float* __restrict__ Wk,
    const float* __restrict__ Wv)
{
    extern __shared__ __half sm[];

    const int n0g  = blockIdx.x * BN;
    const int m0   = blockIdx.y * BM;
    const int widx = n0g >> 10;
    const int col0 = n0g & 1023;

    const float* W   = (widx == 0) ? Wq : (widx == 1) ? Wk : Wv;
    float*       Out = (widx == 0) ? g_Q : (widx == 1) ? g_K : g_V;

    float acc[4][4][4] = {};
    mma_gemm<true>(sm, X + (size_t)m0 * Dd, Dd, W + col0, Dd, Dd / BK, acc);

    const int lane = threadIdx.x & 31, wid = threadIdx.x >> 5;
    const int wm = (wid & 1) * 64, wn = (wid >> 1) * 32;
    #pragma unroll
    for (int im = 0; im < 4; im++)
        #pragma unroll
        for (int in_ = 0; in_ < 4; in_++) {
            const int r0 = m0 + wm + im*16 + (lane >> 2);
            const int c0 = col0 + wn + in_*8 + (lane & 3)*2;
            float2 v0 = {acc[im][in_][0], acc[im][in_][1]};
            float2 v1 = {acc[im][in_][2], acc[im][in_][3]};
            *(float2*)&Out[(size_t)r0 * Dd + c0]       = v0;
            *(float2*)&Out[(size_t)(r0 + 8) * Dd + c0] = v1;
        }
}

// ---------------------------------------------------------------------------
// Kernel 2: scores = (Q.K^T)/32, causal masked.
// ---------------------------------------------------------------------------
__global__ __launch_bounds__(256) void scores_mma(float* __restrict__ Sout)
{
    extern __shared__ __half sm[];

    const int b  = blockIdx.z;
    const int q0 = blockIdx.y * BM;
    const int k0 = blockIdx.x * BN;
    const int tid = threadIdx.x;
    float* Sb = Sout + (size_t)b * Ss * Ss;

    if (k0 > q0 + 127) {                       // fully masked tile
        const float4 z = {0.f, 0.f, 0.f, 0.f};
        for (int t = tid; t < 4096; t += 256) {
            const int r = t >> 5, c4 = (t & 31) * 4;
            *(float4*)&Sb[(size_t)(q0 + r) * Ss + k0 + c4] = z;
        }
        return;
    }

    float acc[4][4][4] = {};
    mma_gemm<false>(sm,
        g_Q + ((size_t)b * Ss + q0) * Dd, Dd,
        g_K + ((size_t)b * Ss + k0) * Dd, Dd,
        Dd / BK, acc);

    const float scale = 0.03125f;
    const int lane = tid & 31, wid = tid >> 5;
    const int wm = (wid & 1) * 64, wn = (wid >> 1) * 32;
    #pragma unroll
    for (int im = 0; im < 4; im++)
        #pragma unroll
        for (int in_ = 0; in_ < 4; in_++) {
            const int q  = q0 + wm + im*16 + (lane >> 2);
            const int kk = k0 + wn + in_*8 + (lane & 3)*2;
            float2 v0, v1;
            v0.x = (kk   <= q)     ? acc[im][in_][0] * scale : 0.f;
            v0.y = (kk+1 <= q)     ? acc[im][in_][1] * scale : 0.f;
            v1.x = (kk   <= q + 8) ? acc[im][in_][2] * scale : 0.f;
            v1.y = (kk+1 <= q + 8) ? acc[im][in_][3] * scale : 0.f;
            *(float2*)&Sb[(size_t)q * Ss + kk]       = v0;
            *(float2*)&Sb[(size_t)(q + 8) * Ss + kk] = v1;
        }
}

// ---------------------------------------------------------------------------
// Kernel 3: causal row softmax, in place.
// ---------------------------------------------------------------------------
__global__ __launch_bounds__(256) void softmax_kernel(float* __restrict__ Sc)
{
    const int row = blockIdx.x;
    const int b = row / Ss;
    const int q = row - b * Ss;
    float* r = Sc + (size_t)b * Ss * Ss + (size_t)q * Ss;
    const int len = q + 1;
    const int t = threadIdx.x;

    __shared__ float red[256];

    float vals[8];
    int n = 0;
    float m = -3.4e38f;
    for (int i = t; i < len; i += 256) { float v = r[i]; vals[n++] = v; m = fmaxf(m, v); }
    red[t] = m; __syncthreads();
    #pragma unroll
    for (int s2 = 128; s2 > 0; s2 >>= 1) {
        if (t < s2) red[t] = fmaxf(red[t], red[t + s2]);
        __syncthreads();
    }
    m = red[0]; __syncthreads();

    float sum = 0.f;
    for (int i = 0; i < n; i++) { vals[i] = __expf(vals[i] - m); sum += vals[i]; }
    red[t] = sum; __syncthreads();
    #pragma unroll
    for (int s2 = 128; s2 > 0; s2 >>= 1) {
        if (t < s2) red[t] += red[t + s2];
        __syncthreads();
    }
    const float inv = 1.0f / red[0];

    n = 0;
    for (int i = t; i < len; i += 256) r[i] = vals[n++] * inv;
}

// ---------------------------------------------------------------------------
// Kernel 4: context = P @ V  (K loop stops past diagonal q-block).
// ---------------------------------------------------------------------------
__global__ __launch_bounds__(256) void context_mma(
    const float* __restrict__ P, float* __restrict__ Ctx)
{
    extern __shared__ __half sm[];

    const int b  = blockIdx.z;
    const int q0 = blockIdx.y * BM;
    const int n0 = blockIdx.x * BN;

    float acc[4][4][4] = {};
    mma_gemm<true>(sm,
        P + (size_t)b * Ss * Ss + (size_t)q0 * Ss, Ss,
        g_V + (size_t)b * Ss * Dd + n0, Dd,
        q0 / BK + 4, acc);

    float* Ob = Ctx + (size_t)b * Ss * Dd;
    const int lane = threadIdx.x & 31, wid = threadIdx.x >> 5;
    const int wm = (wid & 1) * 64, wn = (wid >> 1) * 32;
    #pragma unroll
    for (int im = 0; im < 4; im++)
        #pragma unroll
        for (int in_ = 0; in_ < 4; in_++) {
            const int r0 = q0 + wm + im*16 + (lane >> 2);
            const int c0 = n0 + wn + in_*8 + (lane & 3)*2;
            float2 v0 = {acc[im][in_][0], acc[im][in_][1]};
            float2 v1 = {acc[im][in_][2], acc[im][in_][3]};
            *(float2*)&Ob[(size_t)r0 * Dd + c0]       = v0;
            *(float2*)&Ob[(size_t)(r0 + 8) * Dd + c0] = v1;
        }
}

// ---------------------------------------------------------------------------
extern "C" void kernel_launch(void* const* d_in, const int* in_sizes, int n_in,
                              void* d_out, int out_size)
{
    const float* x  = (const float*)d_in[0];
    const float* Wq = (const float*)d_in[1];
    const float* Wk = (const float*)d_in[2];
    const float* Wv = (const float*)d_in[3];

    float* out = (float*)d_out;
    float* ctx = out;
    float* sc  = out + (size_t)Bb * Ss * Dd;

    cudaFuncSetAttribute(qkv_mma,     cudaFuncAttributeMaxDynamicSharedMemorySize, SMEM_BYTES);
    cudaFuncSetAttribute(scores_mma,  cudaFuncAttributeMaxDynamicSharedMemorySize, SMEM_BYTES);
    cudaFuncSetAttribute(context_mma, cudaFuncAttributeMaxDynamicSharedMemorySize, SMEM_BYTES);

    qkv_mma<<<dim3(3 * Dd / BN, BSs / BM), 256, SMEM_BYTES>>>(x, Wq, Wk, Wv);
    scores_mma<<<dim3(Ss / BN, Ss / BM, Bb), 256, SMEM_BYTES>>>(sc);
    softmax_kernel<<<BSs, 256>>>(sc);
    context_mma<<<dim3(Dd / BN, Ss / BM, Bb), 256, SMEM_BYTES>>>(sc, ctx);
}